// round 1
// baseline (speedup 1.0000x reference)
#include <cuda_runtime.h>

#define PH 7
#define PW 7
#define G  7
#define D  8
#define NB 4
#define C  (D * G * G)      // 392
#define H  96
#define W  96
#define R  512
#define SCALEF 0.0625f
#define OUT_PER_ROI (D * PH * PW)   // 392

__global__ __launch_bounds__(128) void psroi_kernel(
    const float* __restrict__ feat,   // [B, C, H, W]
    const float* __restrict__ rois,   // [R, 5]
    float* __restrict__ out)          // [R, D, PH, PW]
{
    const int r = blockIdx.x;

    __shared__ int   s_b;
    __shared__ int   s_hs[PH], s_he[PH], s_ws[PW], s_we[PW];
    __shared__ float s_invh[PH], s_invw[PW];

    const int t = threadIdx.x;

    if (t == 0) {
        s_b = (int)rois[r * 5 + 0];
    }
    // vertical bins (p -> rows h), threads 0..6
    if (t < PH) {
        const int p = t;
        float y1 = __fmul_rn(rintf(rois[r * 5 + 2]), SCALEF);
        float y2 = __fmul_rn(rintf(__fadd_rn(rois[r * 5 + 4], 1.0f)), SCALEF);
        float rh = fmaxf(__fsub_rn(y2, y1), 0.1f);
        float bs = __fdiv_rn(rh, (float)PH);
        float s  = fminf(fmaxf(floorf(__fadd_rn(__fmul_rn((float)p,       bs), y1)), 0.0f), (float)H);
        float e  = fminf(fmaxf(ceilf (__fadd_rn(__fmul_rn((float)(p + 1), bs), y1)), 0.0f), (float)H);
        s_hs[p] = (int)s;
        s_he[p] = (int)e;
        float n = fmaxf(__fsub_rn(e, s), 0.0f);
        s_invh[p] = 1.0f / fmaxf(n, 1.0f);
    }
    // horizontal bins (q -> cols w), threads 32..38 (separate warp, avoids divergence with above)
    if (t >= 32 && t < 32 + PW) {
        const int q = t - 32;
        float x1 = __fmul_rn(rintf(rois[r * 5 + 1]), SCALEF);
        float x2 = __fmul_rn(rintf(__fadd_rn(rois[r * 5 + 3], 1.0f)), SCALEF);
        float rw = fmaxf(__fsub_rn(x2, x1), 0.1f);
        float bs = __fdiv_rn(rw, (float)PW);
        float s  = fminf(fmaxf(floorf(__fadd_rn(__fmul_rn((float)q,       bs), x1)), 0.0f), (float)W);
        float e  = fminf(fmaxf(ceilf (__fadd_rn(__fmul_rn((float)(q + 1), bs), x1)), 0.0f), (float)W);
        s_ws[q] = (int)s;
        s_we[q] = (int)e;
        float n = fmaxf(__fsub_rn(e, s), 0.0f);
        s_invw[q] = 1.0f / fmaxf(n, 1.0f);
    }
    __syncthreads();

    const float* fb = feat + (size_t)s_b * C * H * W;

    for (int o = t; o < OUT_PER_ROI; o += blockDim.x) {
        const int q = o % PW;
        const int p = (o / PW) % PH;
        const int d = o / (PH * PW);
        const int c = d * G * G + p * G + q;   // position-sensitive channel select
        const float* fc = fb + (size_t)c * H * W;

        const int hs = s_hs[p], he = s_he[p];
        const int ws = s_ws[q], we = s_we[q];

        float sum = 0.0f;
        for (int h = hs; h < he; ++h) {
            const float* row = fc + h * W;
            for (int w = ws; w < we; ++w) {
                sum += __ldg(row + w);
            }
        }
        out[(size_t)r * OUT_PER_ROI + o] = sum * s_invh[p] * s_invw[q];
    }
}

extern "C" void kernel_launch(void* const* d_in, const int* in_sizes, int n_in,
                              void* d_out, int out_size)
{
    const float* feat = (const float*)d_in[0];
    const float* rois = (const float*)d_in[1];
    float* out        = (float*)d_out;
    psroi_kernel<<<R, 128>>>(feat, rois, out);
}

// round 2
// speedup vs baseline: 1.7930x; 1.7930x over previous
#include <cuda_runtime.h>

#define PH 7
#define PW 7
#define G  7
#define D  8
#define C  (D * G * G)      // 392
#define H  96
#define W  96
#define R  512
#define SCALEF 0.0625f
#define OUT_PER_ROI (D * PH * PW)   // 392

__global__ __launch_bounds__(OUT_PER_ROI) void psroi_kernel(
    const float* __restrict__ feat,   // [B, C, H, W]
    const float* __restrict__ rois,   // [R, 5]
    float* __restrict__ out)          // [R, D, PH, PW]
{
    const int r = blockIdx.x;
    const int t = threadIdx.x;

    __shared__ int   s_b;
    __shared__ int   s_hs[PH], s_he[PH], s_ws[PW], s_we[PW];
    __shared__ float s_invh[PH], s_invw[PW];

    if (t == 0) {
        s_b = (int)rois[r * 5 + 0];
    }
    // vertical bins (p -> rows h), threads 0..6
    if (t < PH) {
        const int p = t;
        float y1 = __fmul_rn(rintf(rois[r * 5 + 2]), SCALEF);
        float y2 = __fmul_rn(rintf(__fadd_rn(rois[r * 5 + 4], 1.0f)), SCALEF);
        float rh = fmaxf(__fsub_rn(y2, y1), 0.1f);
        float bs = __fdiv_rn(rh, (float)PH);
        float s  = fminf(fmaxf(floorf(__fadd_rn(__fmul_rn((float)p,       bs), y1)), 0.0f), (float)H);
        float e  = fminf(fmaxf(ceilf (__fadd_rn(__fmul_rn((float)(p + 1), bs), y1)), 0.0f), (float)H);
        s_hs[p] = (int)s;
        s_he[p] = (int)e;
        float n = fmaxf(__fsub_rn(e, s), 0.0f);
        s_invh[p] = 1.0f / fmaxf(n, 1.0f);
    }
    // horizontal bins (q -> cols w), threads 32..38 (separate warp)
    if (t >= 32 && t < 32 + PW) {
        const int q = t - 32;
        float x1 = __fmul_rn(rintf(rois[r * 5 + 1]), SCALEF);
        float x2 = __fmul_rn(rintf(__fadd_rn(rois[r * 5 + 3], 1.0f)), SCALEF);
        float rw = fmaxf(__fsub_rn(x2, x1), 0.1f);
        float bs = __fdiv_rn(rw, (float)PW);
        float s  = fminf(fmaxf(floorf(__fadd_rn(__fmul_rn((float)q,       bs), x1)), 0.0f), (float)W);
        float e  = fminf(fmaxf(ceilf (__fadd_rn(__fmul_rn((float)(q + 1), bs), x1)), 0.0f), (float)W);
        s_ws[q] = (int)s;
        s_we[q] = (int)e;
        float n = fmaxf(__fsub_rn(e, s), 0.0f);
        s_invw[q] = 1.0f / fmaxf(n, 1.0f);
    }
    __syncthreads();

    // one output element per thread: t = d*49 + p*7 + q, which equals the
    // position-sensitive channel index c directly (c = d*G*G + p*G + q).
    const int q = t % PW;
    const int p = (t / PW) % PH;
    const int c = t;                      // == d*G*G + p*G + q

    const float* fc = feat + ((size_t)s_b * C + c) * (H * W);

    const int hs = s_hs[p], he = s_he[p];
    const int ws = s_ws[q], we = s_we[q];

    float sum = 0.0f;
    for (int h = hs; h < he; ++h) {
        const float* row = fc + h * W;
        float rowsum = 0.0f;
        for (int w = ws; w < we; ++w) {
            rowsum += __ldg(row + w);
        }
        sum += rowsum;
    }
    out[(size_t)r * OUT_PER_ROI + t] = sum * s_invh[p] * s_invw[q];
}

extern "C" void kernel_launch(void* const* d_in, const int* in_sizes, int n_in,
                              void* d_out, int out_size)
{
    const float* feat = (const float*)d_in[0];
    const float* rois = (const float*)d_in[1];
    float* out        = (float*)d_out;
    psroi_kernel<<<R, OUT_PER_ROI>>>(feat, rois, out);
}